// round 16
// speedup vs baseline: 2.6403x; 1.0073x over previous
#include <cuda_runtime.h>
#include <cstdint>
#include <cstddef>

// Problem constants
#define CB 8
#define CS 512
#define CE 512
#define CH 8
#define CD 64
#define CP 64
#define CF 2048
#define CNR 129            // 2P+1
#define CSR 192            // padded rows for pos_emb
#define CBH (CB*CH)        // 64
#define CM (CB*CS)         // 4096

// ---------------- device scratch (zero-initialized .bss) ----------------------
__device__ __align__(16) float g_q[CBH*CS*CD];
__device__ __align__(16) float g_k[CBH*CS*CD];
__device__ __align__(16) float g_v[CBH*CS*CD];
__device__ __align__(16) float g_pe[CSR*CD];            // padded pos_emb (rows >=129 zero)
__device__ __align__(16) float g_concat[CM*CE];         // rounded at write
__device__ __align__(16) float g_t1[CM*CE];
__device__ __align__(16) float g_attnout[CM*CE];        // fp32 (resid)
__device__ __align__(16) float g_attnout_r[CM*CE];      // RN-rounded (FFN1 A)
__device__ __align__(16) float g_hidden[CM*CF];         // rounded at write
__device__ __align__(16) float g_t2[CM*CE];             // split-K partial 0
__device__ __align__(16) float g_t2b[CM*CE];            // split-K partial 1
__device__ __align__(16) float g_wqkv[CE*3*CE];         // packed+rounded [512][1536]
__device__ __align__(16) float g_bqkv[3*CE];
__device__ __align__(16) float g_wor[CE*CE];            // rounded wo
__device__ __align__(16) float g_w1r[CE*CF];            // rounded w1
__device__ __align__(16) float g_w2r[CF*CE];            // rounded w2

enum { EPI_QKV = 0, EPI_RESID = 1, EPI_RELU = 2, EPI_NONE = 3 };

__device__ __forceinline__ uint32_t f2tf(float f) {
    uint32_t u;
    asm("cvt.rna.tf32.f32 %0, %1;" : "=r"(u) : "f"(f));
    return u;
}
__device__ __forceinline__ float roundtf(float f) {
    return __uint_as_float(f2tf(f));
}

__device__ __forceinline__ void mma_tf32(float c[4], const uint32_t a[4],
                                         const uint32_t b[2]) {
    asm volatile(
        "mma.sync.aligned.m16n8k8.row.col.f32.tf32.tf32.f32 "
        "{%0,%1,%2,%3}, {%4,%5,%6,%7}, {%8,%9}, {%0,%1,%2,%3};\n"
        : "+f"(c[0]), "+f"(c[1]), "+f"(c[2]), "+f"(c[3])
        : "r"(a[0]), "r"(a[1]), "r"(a[2]), "r"(a[3]), "r"(b[0]), "r"(b[1]));
}

__device__ __forceinline__ void cp16(uint32_t dst, const void* src) {
    asm volatile("cp.async.cg.shared.global [%0], [%1], 16;\n" :: "r"(dst), "l"(src));
}
__device__ __forceinline__ void cp_commit() {
    asm volatile("cp.async.commit_group;\n");
}
template<int N>
__device__ __forceinline__ void cp_wait() {
    asm volatile("cp.async.wait_group %0;\n" :: "n"(N));
}

// ---------------- TF32 tensor-core GEMM (cp.async 3-stage, BK=32) -------------
#define APITCH 36
#define GEMM_NSTAGE 3

template<int BN>
__global__ __launch_bounds__(256, 2) void mma_gemm_kernel(
    const float* __restrict__ A, const float* __restrict__ Bm,
    float* __restrict__ C, float* __restrict__ C2, float* __restrict__ C3,
    int M, int N, int K, int Kstride,
    const float* __restrict__ bias, const float* __restrict__ resid, int mode)
{
    constexpr int BPITCH = BN + 4;
    constexpr int NT = BN / 16;
    constexpr int ASZ = 128 * APITCH;
    constexpr int BSZ = 32 * BPITCH;
    constexpr int CPR = BN / 4;
    constexpr int NBL = CPR / 8;
    extern __shared__ uint32_t smem_u[];
    uint32_t* As = smem_u;
    uint32_t* Bs = smem_u + GEMM_NSTAGE * ASZ;

    const int tid = threadIdx.x;
    const int warp = tid >> 5;
    const int lane = tid & 31;
    const int gid = lane >> 2;
    const int tig = lane & 3;
    const int wy = warp >> 1;
    const int wx = warp & 1;
    const int bm = blockIdx.y * 128;
    const int bn = blockIdx.x * BN;
    const int koff = blockIdx.z * K;

    const uint32_t a_base = (uint32_t)__cvta_generic_to_shared(As);
    const uint32_t b_base = (uint32_t)__cvta_generic_to_shared(Bs);

    const int nk = K >> 5;

    auto stageg = [&](int s) {
        const int bs = s % GEMM_NSTAGE;
        const uint32_t adst = a_base + bs * ASZ * 4;
        const uint32_t bdst = b_base + bs * BSZ * 4;
#pragma unroll
        for (int l = 0; l < 4; l++) {
            const int idx = tid + (l << 8);
            const int r = idx >> 3;
            const int c = (idx & 7) << 2;
            cp16(adst + (r * APITCH + c) * 4,
                 A + (size_t)(bm + r) * Kstride + koff + (s << 5) + c);
        }
#pragma unroll
        for (int l = 0; l < NBL; l++) {
            const int idx = tid + (l << 8);
            const int r = idx / CPR;
            const int c = (idx % CPR) << 2;
            cp16(bdst + (r * BPITCH + c) * 4,
                 Bm + (size_t)(koff + (s << 5) + r) * N + bn + c);
        }
    };

    float acc[2][NT][4];
#pragma unroll
    for (int mt = 0; mt < 2; mt++)
#pragma unroll
        for (int nt = 0; nt < NT; nt++)
#pragma unroll
            for (int r = 0; r < 4; r++) acc[mt][nt][r] = 0.0f;

#pragma unroll
    for (int s = 0; s < GEMM_NSTAGE - 1; s++) {
        if (s < nk) stageg(s);
        cp_commit();
    }

    for (int i = 0; i < nk; i++) {
        cp_wait<1>();
        __syncthreads();
        if (i + 2 < nk) stageg(i + 2);
        cp_commit();

        const int buf = i % GEMM_NSTAGE;
        const uint32_t* Ab = As + buf * ASZ;
        const uint32_t* Bb = Bs + buf * BSZ;
#pragma unroll
        for (int ks = 0; ks < 32; ks += 8) {
            uint32_t af[2][4];
#pragma unroll
            for (int mt = 0; mt < 2; mt++) {
                const int mrow = wy * 32 + mt * 16 + gid;
                af[mt][0] = Ab[mrow * APITCH + ks + tig];
                af[mt][1] = Ab[(mrow + 8) * APITCH + ks + tig];
                af[mt][2] = Ab[mrow * APITCH + ks + tig + 4];
                af[mt][3] = Ab[(mrow + 8) * APITCH + ks + tig + 4];
            }
            uint32_t bf[NT][2];
#pragma unroll
            for (int nt = 0; nt < NT; nt++) {
                const int nc = wx * (BN / 2) + nt * 8 + gid;
                bf[nt][0] = Bb[(ks + tig) * BPITCH + nc];
                bf[nt][1] = Bb[(ks + tig + 4) * BPITCH + nc];
            }
#pragma unroll
            for (int mt = 0; mt < 2; mt++)
#pragma unroll
                for (int nt = 0; nt < NT; nt++)
                    mma_tf32(acc[mt][nt], af[mt], bf[nt]);
        }
    }

    float* Csel = (mode == EPI_NONE && blockIdx.z) ? C2 : C;
#pragma unroll
    for (int mt = 0; mt < 2; mt++) {
#pragma unroll
        for (int nt = 0; nt < NT; nt++) {
            const int col = bn + wx * (BN / 2) + nt * 8 + 2 * tig;
            float bv0 = 0.0f, bv1 = 0.0f;
            if (bias) { bv0 = bias[col]; bv1 = bias[col + 1]; }
#pragma unroll
            for (int half = 0; half < 2; half++) {
                const int row = bm + wy * 32 + mt * 16 + gid + half * 8;
                float v0 = acc[mt][nt][half * 2 + 0] + bv0;
                float v1 = acc[mt][nt][half * 2 + 1] + bv1;
                if (mode == EPI_RESID) {
                    v0 += resid[(size_t)row * N + col];
                    v1 += resid[(size_t)row * N + col + 1];
                } else if (mode == EPI_RELU) {
                    v0 = roundtf(fmaxf(v0, 0.0f));
                    v1 = roundtf(fmaxf(v1, 0.0f));
                }
                float2 vv = {v0, v1};
                if (mode == EPI_QKV) {
                    const int b = row >> 9, ii = row & 511;
                    const int which = col >> 9;
                    const int cc = col & 511;
                    const int h = cc >> 6, d = cc & 63;
                    float* base = (which == 0) ? C : (which == 1) ? C2 : C3;
                    *(float2*)(base + (((size_t)(b * CH + h) * CS) + ii) * CD + d) = vv;
                } else {
                    *(float2*)(Csel + (size_t)row * N + col) = vv;
                }
            }
        }
    }
}

#define GEMM_SMEM_BYTES(BN) (GEMM_NSTAGE * (128 * APITCH + 32 * ((BN) + 4)) * 4)

// ---------------- merged round-copy (3 weight arrays) --------------------------
__global__ void round3_kernel(const float4* __restrict__ s1, float4* __restrict__ d1, int n1,
                              const float4* __restrict__ s2, float4* __restrict__ d2, int n2,
                              const float4* __restrict__ s3, float4* __restrict__ d3, int n3)
{
    int i = blockIdx.x * 256 + threadIdx.x;
    const float4* s; float4* d;
    if (i < n1) { s = s1 + i; d = d1 + i; }
    else {
        i -= n1;
        if (i < n2) { s = s2 + i; d = d2 + i; }
        else {
            i -= n2;
            if (i >= n3) return;
            s = s3 + i; d = d3 + i;
        }
    }
    float4 v = *s;
    v.x = roundtf(v.x); v.y = roundtf(v.y);
    v.z = roundtf(v.z); v.w = roundtf(v.w);
    *d = v;
}

// ---------------- pack QKV weights/biases (rounded) + pe copy ------------------
__global__ void pack_qkv_kernel(const float* __restrict__ wq, const float* __restrict__ wk,
                                const float* __restrict__ wv, const float* __restrict__ bq,
                                const float* __restrict__ bk, const float* __restrict__ bv,
                                const float* __restrict__ pe)
{
    int idx = blockIdx.x * 256 + threadIdx.x;
    if (idx < CE * CE) {
        int r = idx >> 9, c = idx & 511;
        g_wqkv[(size_t)r * 1536 + c] = roundtf(wq[idx]);
        g_wqkv[(size_t)r * 1536 + 512 + c] = roundtf(wk[idx]);
        g_wqkv[(size_t)r * 1536 + 1024 + c] = roundtf(wv[idx]);
    }
    if (idx < CE) {
        g_bqkv[idx] = bq[idx];
        g_bqkv[512 + idx] = bk[idx];
        g_bqkv[1024 + idx] = bv[idx];
    }
    if (idx < CNR * CD) g_pe[idx] = pe[idx];
}

// ---------------- FULLY FUSED attention (Q fragments hoisted to regs) ----------
#define FS_Q 0
#define FS_K 4224
#define FS_QZ 21632
#define FS_INT 25856
#define FS_RED 26912
#define FS_SMEM_BYTES (27040 * 4)
#define FS_KBUF (128*68)

__global__ __launch_bounds__(256, 2) void fused_attn_kernel(
    const float* __restrict__ dist, const int* __restrict__ dt,
    const int* __restrict__ mask)
{
    extern __shared__ uint32_t sm[];
    uint32_t* Qs = sm + FS_Q;
    float* AW = (float*)(sm + FS_Q);
    uint32_t* Kb = sm + FS_K;
    float* QZs = (float*)(sm + FS_QZ);
    int* dti_s = (int*)(sm + FS_INT);
    int* dtj_s = dti_s + 32;
    int* mj_s = dtj_s + 512;
    float* red = (float*)(sm + FS_RED);

    const int bh = blockIdx.y;
    const int b = bh >> 3, h = bh & 7;
    const int i0 = blockIdx.x << 5;
    const int tid = threadIdx.x;
    const int warp = tid >> 5;
    const int lane = tid & 31;
    const int gid = lane >> 2;
    const int tig = lane & 3;
    const int wm = warp & 1;
    const int wn = warp >> 1;
    const int mrow = wm * 16 + gid;

    const float* qb = g_q + (size_t)bh * CS * CD;
    const float* kb = g_k + (size_t)bh * CS * CD;
    const float* vb = g_v + (size_t)bh * CS * CD;

    const uint32_t q_base = (uint32_t)__cvta_generic_to_shared(Qs);
    const uint32_t k_base = (uint32_t)__cvta_generic_to_shared(Kb);

#pragma unroll
    for (int l = 0; l < 2; l++) {
        const int idx = tid + (l << 8);
        const int r = idx >> 4;
        const int c = (idx & 15) << 2;
        cp16(q_base + (r * 68 + c) * 4, qb + (size_t)(i0 + r) * CD + c);
    }
    for (int t = tid; t < 160 * 16; t += 256) {
        const int r = t >> 4;
        const int c = (t & 15) << 2;
        cp16(k_base + (r * 68 + c) * 4, g_pe + (size_t)r * CD + c);
    }
    cp_commit();

    if (tid < 32) dti_s[tid] = dt[b * CS + i0 + tid];
    {
        int2 dj = *(const int2*)&dt[b * CS + 2 * tid];
        dtj_s[2 * tid] = dj.x; dtj_s[2 * tid + 1] = dj.y;
        int2 mm = *(const int2*)&mask[b * CS + 2 * tid];
        mj_s[2 * tid] = mm.x; mj_s[2 * tid + 1] = mm.y;
    }
    cp_wait<0>();
    __syncthreads();

    // hoist Q fragments into registers (used by phase 1 and all 4 score chunks)
    uint32_t qf[8][4];
#pragma unroll
    for (int k8 = 0; k8 < 8; k8++) {
        const int ks = k8 << 3;
        qf[k8][0] = Qs[mrow * 68 + ks + tig];
        qf[k8][1] = Qs[(mrow + 8) * 68 + ks + tig];
        qf[k8][2] = Qs[mrow * 68 + ks + tig + 4];
        qf[k8][3] = Qs[(mrow + 8) * 68 + ks + tig + 4];
    }

    // ---- phase 1: qz
    {
        float qacc[5][4];
#pragma unroll
        for (int nt = 0; nt < 5; nt++)
#pragma unroll
            for (int r = 0; r < 4; r++) qacc[nt][r] = 0.0f;
#pragma unroll
        for (int k8 = 0; k8 < 8; k8++) {
            const int ks = k8 << 3;
#pragma unroll
            for (int nt = 0; nt < 5; nt++) {
                const int nc = wn * 40 + nt * 8 + gid;
                uint32_t bf[2];
                bf[0] = Kb[nc * 68 + ks + tig];
                bf[1] = Kb[nc * 68 + ks + tig + 4];
                mma_tf32(qacc[nt], qf[k8], bf);
            }
        }
        __syncthreads();

#pragma unroll
        for (int l = 0; l < 8; l++) {
            const int idx = tid + (l << 8);
            const int r = idx >> 4;
            const int c = (idx & 15) << 2;
            cp16(k_base + (r * 68 + c) * 4, kb + (size_t)r * CD + c);
        }
        cp_commit();

#pragma unroll
        for (int nt = 0; nt < 5; nt++) {
            const int col = wn * 40 + nt * 8 + 2 * tig;
            if (col <= 128) {
                QZs[mrow * 132 + col] = qacc[nt][0];
                QZs[mrow * 132 + col + 1] = qacc[nt][1];
                QZs[(mrow + 8) * 132 + col] = qacc[nt][2];
                QZs[(mrow + 8) * 132 + col + 1] = qacc[nt][3];
            }
        }
    }

    // ---- phase 2: scores (Q from regs, dist prefetched)
    float sacc[4][4][4];
#pragma unroll
    for (int c = 0; c < 4; c++)
#pragma unroll
        for (int nt = 0; nt < 4; nt++)
#pragma unroll
            for (int r = 0; r < 4; r++) sacc[c][nt][r] = 0.0f;

#pragma unroll
    for (int ch = 0; ch < 4; ch++) {
        cp_wait<0>();
        __syncthreads();
        if (ch < 3) {
            const uint32_t kdst = k_base + (((ch + 1) & 1)) * FS_KBUF * 4;
#pragma unroll
            for (int l = 0; l < 8; l++) {
                const int idx = tid + (l << 8);
                const int r = idx >> 4;
                const int c = (idx & 15) << 2;
                cp16(kdst + (r * 68 + c) * 4,
                     kb + (size_t)((ch + 1) * 128 + r) * CD + c);
            }
        }
        cp_commit();

        float2 dv[2][4];
#pragma unroll
        for (int half = 0; half < 2; half++) {
            const int i = i0 + mrow + half * 8;
#pragma unroll
            for (int nt = 0; nt < 4; nt++) {
                const int jl = ch * 128 + wn * 32 + nt * 8 + 2 * tig;
                dv[half][nt] = *(const float2*)&dist[((size_t)b * CS + i) * CS + jl];
            }
        }

        const uint32_t* Kc = Kb + (ch & 1) * FS_KBUF;
#pragma unroll
        for (int k8 = 0; k8 < 8; k8++) {
            const int ks = k8 << 3;
#pragma unroll
            for (int nt = 0; nt < 4; nt++) {
                const int nc = wn * 32 + nt * 8 + gid;
                uint32_t bf[2];
                bf[0] = Kc[nc * 68 + ks + tig];
                bf[1] = Kc[nc * 68 + ks + tig + 4];
                mma_tf32(sacc[ch][nt], qf[k8], bf);
            }
        }

#pragma unroll
        for (int half = 0; half < 2; half++) {
            const int il = mrow + half * 8;
            const int di = dti_s[il];
#pragma unroll
            for (int nt = 0; nt < 4; nt++) {
                const int jl = ch * 128 + wn * 32 + nt * 8 + 2 * tig;
#pragma unroll
                for (int u = 0; u < 2; u++) {
                    const int j = jl + u;
                    int rel = min(max(dtj_s[j] - di, -CP), CP) + CP;
                    float v = (sacc[ch][nt][half * 2 + u] + QZs[il * 132 + rel]) * 0.125f
                            + 0.6f * (u ? dv[half][nt].y : dv[half][nt].x);
                    if (mj_s[j] == 0) v = -1e9f;
                    sacc[ch][nt][half * 2 + u] = v;
                }
            }
        }
    }
    __syncthreads();

    // ---- phase 3: softmax + bins
    float* bins = QZs;
    for (int t = tid; t < 32 * 132; t += 256) bins[t] = 0.0f;

    float mrw[2];
#pragma unroll
    for (int half = 0; half < 2; half++) {
        float m = -1e30f;
#pragma unroll
        for (int c = 0; c < 4; c++)
#pragma unroll
            for (int nt = 0; nt < 4; nt++) {
                m = fmaxf(m, sacc[c][nt][half * 2]);
                m = fmaxf(m, sacc[c][nt][half * 2 + 1]);
            }
        m = fmaxf(m, __shfl_xor_sync(0xffffffffu, m, 1));
        m = fmaxf(m, __shfl_xor_sync(0xffffffffu, m, 2));
        mrw[half] = m;
    }
    if (tig == 0) {
        red[wn * 32 + mrow] = mrw[0];
        red[wn * 32 + mrow + 8] = mrw[1];
    }
    __syncthreads();
#pragma unroll
    for (int half = 0; half < 2; half++) {
        const int r = mrow + half * 8;
        mrw[half] = fmaxf(fmaxf(red[r], red[32 + r]), fmaxf(red[64 + r], red[96 + r]));
    }
    __syncthreads();

    float srow[2] = {0.0f, 0.0f};
#pragma unroll
    for (int half = 0; half < 2; half++) {
#pragma unroll
        for (int c = 0; c < 4; c++)
#pragma unroll
            for (int nt = 0; nt < 4; nt++)
#pragma unroll
                for (int u = 0; u < 2; u++) {
                    float e = __expf(sacc[c][nt][half * 2 + u] - mrw[half]);
                    sacc[c][nt][half * 2 + u] = e;
                    srow[half] += e;
                }
        srow[half] += __shfl_xor_sync(0xffffffffu, srow[half], 1);
        srow[half] += __shfl_xor_sync(0xffffffffu, srow[half], 2);
    }
    if (tig == 0) {
        red[wn * 32 + mrow] = srow[0];
        red[wn * 32 + mrow + 8] = srow[1];
    }
    __syncthreads();
    float inv2[2];
#pragma unroll
    for (int half = 0; half < 2; half++) {
        const int r = mrow + half * 8;
        inv2[half] = 1.0f / (red[r] + red[32 + r] + red[64 + r] + red[96 + r]);
    }

#pragma unroll
    for (int half = 0; half < 2; half++) {
        const int il = mrow + half * 8;
        const int di = dti_s[il];
#pragma unroll
        for (int c = 0; c < 4; c++)
#pragma unroll
            for (int nt = 0; nt < 4; nt++) {
                const int jl = c * 128 + wn * 32 + nt * 8 + 2 * tig;
                float a0 = sacc[c][nt][half * 2 + 0] * inv2[half];
                float a1 = sacc[c][nt][half * 2 + 1] * inv2[half];
                sacc[c][nt][half * 2 + 0] = a0;
                sacc[c][nt][half * 2 + 1] = a1;
                int r0 = min(max(dtj_s[jl] - di, -CP), CP) + CP;
                int r1 = min(max(dtj_s[jl + 1] - di, -CP), CP) + CP;
                atomicAdd(&bins[il * 132 + r0], a0);
                atomicAdd(&bins[il * 132 + r1], a1);
            }
    }
    __syncthreads();

    // ---- phase 5: out = aw @ V + bins @ PE (2-way k-split across warp halves)
    const int wk = warp >> 2;
    const int wq = warp & 3;
    const int wm2 = wq >> 1;
    const int wn2 = wq & 1;
    const int mrow2 = wm2 * 16 + gid;

    float oacc[4][4];
#pragma unroll
    for (int nt = 0; nt < 4; nt++)
#pragma unroll
        for (int r = 0; r < 4; r++) oacc[nt][r] = 0.0f;

#pragma unroll
    for (int l = 0; l < 8; l++) {
        const int idx = tid + (l << 8);
        const int r = idx >> 4;
        const int c = (idx & 15) << 2;
        cp16(k_base + (r * 68 + c) * 4, vb + (size_t)r * CD + c);
    }
    cp_commit();

#pragma unroll
    for (int ch = 0; ch < 4; ch++) {
#pragma unroll
        for (int half = 0; half < 2; half++) {
            const int il = mrow + half * 8;
#pragma unroll
            for (int nt = 0; nt < 4; nt++) {
                const int jloc = wn * 32 + nt * 8 + 2 * tig;
                float2 st = {sacc[ch][nt][half * 2 + 0], sacc[ch][nt][half * 2 + 1]};
                *(float2*)&AW[il * 132 + jloc] = st;
            }
        }
        cp_wait<0>();
        __syncthreads();
        if (ch < 3) {
            const uint32_t vdst = k_base + ((ch + 1) & 1) * FS_KBUF * 4;
#pragma unroll
            for (int l = 0; l < 8; l++) {
                const int idx = tid + (l << 8);
                const int r = idx >> 4;
                const int c = (idx & 15) << 2;
                cp16(vdst + (r * 68 + c) * 4,
                     vb + (size_t)((ch + 1) * 128 + r) * CD + c);
            }
        }
        cp_commit();

        const uint32_t* Vc = Kb + (ch & 1) * FS_KBUF;
        const uint32_t* AWu = (const uint32_t*)AW;
#pragma unroll
        for (int ks = 0; ks < 64; ks += 8) {
            const int kk = wk * 64 + ks;
            uint32_t af[4];
            af[0] = AWu[mrow2 * 132 + kk + tig];
            af[1] = AWu[(mrow2 + 8) * 132 + kk + tig];
            af[2] = AWu[mrow2 * 132 + kk + tig + 4];
            af[3] = AWu[(mrow2 + 8) * 132 + kk + tig + 4];
#pragma unroll
            for (int nt = 0; nt < 4; nt++) {
                const int nc = wn2 * 32 + nt * 8 + gid;
                uint32_t bf[2];
                bf[0] = Vc[(kk + tig) * 68 + nc];
                bf[1] = Vc[(kk + tig + 4) * 68 + nc];
                mma_tf32(oacc[nt], af, bf);
            }
        }
        __syncthreads();
    }

    // PE part (k-split)
    {
#pragma unroll
        for (int l = 0; l < 4; l++) {
            const int idx = tid + (l << 8);
            const int r = idx >> 4;
            const int c = (idx & 15) << 2;
            cp16(k_base + (r * 68 + c) * 4, g_pe + (size_t)r * CD + c);
        }
        cp_commit();

        const uint32_t* binsu = (const uint32_t*)bins;
#pragma unroll
        for (int pch = 0; pch < 3; pch++) {
            cp_wait<0>();
            __syncthreads();
            if (pch < 2) {
                const uint32_t pdst = k_base + ((pch + 1) & 1) * FS_KBUF * 4;
#pragma unroll
                for (int l = 0; l < 4; l++) {
                    const int idx = tid + (l << 8);
                    const int r = idx >> 4;
                    const int c = (idx & 15) << 2;
                    cp16(pdst + (r * 68 + c) * 4,
                         g_pe + (size_t)((pch + 1) * 64 + r) * CD + c);
                }
            }
            cp_commit();

            const uint32_t* Pc = Kb + (pch & 1) * FS_KBUF;
#pragma unroll
            for (int ks = 0; ks < 32; ks += 8) {
                const int kl = wk * 32 + ks;
                const int kk = pch * 64 + kl;
                uint32_t af[4];
                af[0] = binsu[mrow2 * 132 + kk + tig];
                af[1] = binsu[(mrow2 + 8) * 132 + kk + tig];
                af[2] = binsu[mrow2 * 132 + kk + tig + 4];
                af[3] = binsu[(mrow2 + 8) * 132 + kk + tig + 4];
#pragma unroll
                for (int nt = 0; nt < 4; nt++) {
                    const int nc = wn2 * 32 + nt * 8 + gid;
                    uint32_t bf[2];
                    bf[0] = Pc[(kl + tig) * 68 + nc];
                    bf[1] = Pc[(kl + tig + 4) * 68 + nc];
                    mma_tf32(oacc[nt], af, bf);
                }
            }
        }
    }
    __syncthreads();

    float* redk = AW;
    if (wk == 1) {
#pragma unroll
        for (int nt = 0; nt < 4; nt++) {
            float4 p = {oacc[nt][0], oacc[nt][1], oacc[nt][2], oacc[nt][3]};
            *(float4*)&redk[(wq * 4 + nt) * 128 + lane * 4] = p;
        }
    }
    __syncthreads();
    if (wk == 0) {
#pragma unroll
        for (int nt = 0; nt < 4; nt++) {
            float4 p = *(const float4*)&redk[(wq * 4 + nt) * 128 + lane * 4];
            oacc[nt][0] += p.x; oacc[nt][1] += p.y;
            oacc[nt][2] += p.z; oacc[nt][3] += p.w;
        }
#pragma unroll
        for (int nt = 0; nt < 4; nt++) {
            const int col = h * CD + wn2 * 32 + nt * 8 + 2 * tig;
#pragma unroll
            for (int half = 0; half < 2; half++) {
                const int row = i0 + mrow2 + half * 8;
                float2 vv = {roundtf(oacc[nt][half * 2 + 0]),
                             roundtf(oacc[nt][half * 2 + 1])};
                *(float2*)&g_concat[(size_t)(b * CS + row) * CE + col] = vv;
            }
        }
    }
}

// ---------------- layernorm: in (+ in2 + addv + resid) -> LN -------------------
__global__ __launch_bounds__(256) void ln_kernel(
    const float* __restrict__ in, const float* __restrict__ in2,
    const float* __restrict__ addv, const float* __restrict__ resid,
    float* __restrict__ out, float* __restrict__ out_r,
    const float* __restrict__ gg, const float* __restrict__ bb)
{
    const int row = blockIdx.x;
    const int tid = threadIdx.x;
    const int lane = tid & 31;
    const int wid = tid >> 5;
    __shared__ float wred[8];
    __shared__ float stat;

    float2 v = *(const float2*)&in[(size_t)row * CE + 2 * tid];
    if (in2) {
        float2 v2 = *(const float2*)&in2[(size_t)row * CE + 2 * tid];
        v.x += v2.x; v.y += v2.y;
    }
    if (addv) {
        float2 av = *(const float2*)&addv[2 * tid];
        v.x += av.x; v.y += av.y;
    }
    if (resid) {
        float2 rv = *(const float2*)&resid[(size_t)row * CE + 2 * tid];
        v.x += rv.x; v.y += rv.y;
    }
    float s = v.x + v.y;
#pragma unroll
    for (int o = 16; o > 0; o >>= 1) s += __shfl_xor_sync(0xffffffffu, s, o);
    if (lane == 0) wred[wid] = s;
    __syncthreads();
    if (tid == 0) {
        float ss = wred[0];
#pragma unroll
        for (int k = 1; k < 8; k++) ss += wred[k];
        stat = ss * (1.0f / CE);
    }
    __syncthreads();
    const float mu = stat;
    const float d0 = v.x - mu, d1 = v.y - mu;
    float q = d0 * d0 + d1 * d1;
#pragma unroll
    for (int o = 16; o > 0; o >>= 1) q += __shfl_xor_sync(0xffffffffu, q, o);
    if (lane == 0) wred[wid] = q;
    __syncthreads();
    if (tid == 0) {
        float qq = wred[0];
#pragma unroll
        for (int k = 1; k < 8; k++) qq += wred[k];
        stat = rsqrtf(qq * (1.0f / CE) + 1e-5f);
    }
    __syncthreads();
    const float rstd = stat;
    float2 gv = *(const float2*)&gg[2 * tid];
    float2 bv = *(const float2*)&bb[2 * tid];
    float2 ov = {d0 * rstd * gv.x + bv.x, d1 * rstd * gv.y + bv.y};
    *(float2*)&out[(size_t)row * CE + 2 * tid] = ov;
    if (out_r) {
        float2 orr = {roundtf(ov.x), roundtf(ov.y)};
        *(float2*)&out_r[(size_t)row * CE + 2 * tid] = orr;
    }
}

// ---------------- launch -------------------------------------------------------
extern "C" void kernel_launch(void* const* d_in, const int* in_sizes, int n_in,
                              void* d_out, int out_size)
{
    const float* x    = (const float*)d_in[0];
    const float* dist = (const float*)d_in[1];
    const int*   dt   = (const int*)d_in[2];
    const int*   mask = (const int*)d_in[3];
    const float* wq_w = (const float*)d_in[4];
    const float* wq_b = (const float*)d_in[5];
    const float* wk_w = (const float*)d_in[6];
    const float* wk_b = (const float*)d_in[7];
    const float* wv_w = (const float*)d_in[8];
    const float* wv_b = (const float*)d_in[9];
    const float* wo_w = (const float*)d_in[10];
    const float* wo_b = (const float*)d_in[11];
    const float* pe   = (const float*)d_in[12];
    const float* w1   = (const float*)d_in[13];
    const float* b1   = (const float*)d_in[14];
    const float* w2   = (const float*)d_in[15];
    const float* b2   = (const float*)d_in[16];
    const float* ln1g = (const float*)d_in[17];
    const float* ln1b = (const float*)d_in[18];
    const float* ln2g = (const float*)d_in[19];
    const float* ln2b = (const float*)d_in[20];
    float* out = (float*)d_out;

    void *pq, *pk, *pv, *pcc, *pt1, *pao, *paor, *phid, *pt2, *pt2b, *pwqkv, *pbqkv;
    void *pwor, *pw1r, *pw2r;
    cudaGetSymbolAddress(&pq, g_q);
    cudaGetSymbolAddress(&pk, g_k);
    cudaGetSymbolAddress(&pv, g_v);
    cudaGetSymbolAddress(&pcc, g_concat);
    cudaGetSymbolAddress(&pt1, g_t1);
    cudaGetSymbolAddress(&pao, g_attnout);
    cudaGetSymbolAddress(&paor, g_attnout_r);
    cudaGetSymbolAddress(&phid, g_hidden);
    cudaGetSymbolAddress(&pt2, g_t2);
    cudaGetSymbolAddress(&pt2b, g_t2b);
    cudaGetSymbolAddress(&pwqkv, g_wqkv);
    cudaGetSymbolAddress(&pbqkv, g_bqkv);
    cudaGetSymbolAddress(&pwor, g_wor);
    cudaGetSymbolAddress(&pw1r, g_w1r);
    cudaGetSymbolAddress(&pw2r, g_w2r);

    cudaFuncSetAttribute(fused_attn_kernel,
                         cudaFuncAttributeMaxDynamicSharedMemorySize, FS_SMEM_BYTES);
    cudaFuncSetAttribute(mma_gemm_kernel<128>,
                         cudaFuncAttributeMaxDynamicSharedMemorySize, GEMM_SMEM_BYTES(128));

    pack_qkv_kernel<<<(CE * CE + 255) / 256, 256>>>(wq_w, wk_w, wv_w, wq_b, wk_b, wv_b, pe);
    {
        const int n1 = CE * CE / 4, n2 = CE * CF / 4, n3 = CF * CE / 4;
        const int ntot = n1 + n2 + n3;
        round3_kernel<<<(ntot + 255) / 256, 256>>>(
            (const float4*)wo_w, (float4*)pwor, n1,
            (const float4*)w1, (float4*)pw1r, n2,
            (const float4*)w2, (float4*)pw2r, n3);
    }

    // fused QKV: M=4096, N=1536, K=512 (A = raw x)
    dim3 gq(1536 / 128, CM / 128);
    mma_gemm_kernel<128><<<gq, 256, GEMM_SMEM_BYTES(128)>>>(
        x, (const float*)pwqkv, (float*)pq, (float*)pk, (float*)pv,
        CM, 1536, CE, CE, (const float*)pbqkv, nullptr, EPI_QKV);

    // fully fused attention -> g_concat
    dim3 gfs(CS / 32, CBH);
    fused_attn_kernel<<<gfs, 256, FS_SMEM_BYTES>>>(dist, dt, mask);

    // wo: split-K=2 -> partials t1/t2b; reduce + bias + resid in ln1
    dim3 gwo(CE / 128, CM / 128, 2);
    mma_gemm_kernel<128><<<gwo, 256, GEMM_SMEM_BYTES(128)>>>(
        (const float*)pcc, (const float*)pwor, (float*)pt1, (float*)pt2b, nullptr,
        CM, CE, CE / 2, CE, nullptr, nullptr, EPI_NONE);
    ln_kernel<<<CM, 256>>>((const float*)pt1, (const float*)pt2b, wo_b, x,
                           (float*)pao, (float*)paor, ln1g, ln1b);

    dim3 gf1(CF / 128, CM / 128);
    mma_gemm_kernel<128><<<gf1, 256, GEMM_SMEM_BYTES(128)>>>(
        (const float*)paor, (const float*)pw1r, (float*)phid, nullptr, nullptr,
        CM, CF, CE, CE, b1, nullptr, EPI_RELU);

    // FFN2 split-K=2: partials -> t2 / t2b
    dim3 gf2(CE / 128, CM / 128, 2);
    mma_gemm_kernel<128><<<gf2, 256, GEMM_SMEM_BYTES(128)>>>(
        (const float*)phid, (const float*)pw2r, (float*)pt2, (float*)pt2b, nullptr,
        CM, CE, CF / 2, CF, nullptr, nullptr, EPI_NONE);

    ln_kernel<<<CM, 256>>>((const float*)pt2, (const float*)pt2b, b2, (const float*)pao,
                           out, nullptr, ln2g, ln2b);
}